// round 4
// baseline (speedup 1.0000x reference)
#include <cuda_runtime.h>

// AttentionAggregator: out[n] = sum_k softmax_k(feats[n,k]·w) * feats[n,k],
// feats[n,k] = embed_table[neigh_idx[n,k]].
// table [VOCAB,128] f32, attn_w [128] f32, neigh_idx [N,10] (int32 or int64), out [N,128] f32.
//
// R4: occupancy-oriented rewrite.
//  - indices normalized to int32 scratch (removes dual-path + 64-bit math from hot kernel)
//  - 2 gathered rows in registers, 8 staged in lane-private shared memory
//  - __launch_bounds__(256,6) -> <=40 regs -> 48 warps/SM
//  - streaming output stores to protect L2 residency of the table

#define K_NEIGH 10
#define WARPS_PER_BLOCK 8
#define REG_ROWS 2
#define SMEM_ROWS (K_NEIGH - REG_ROWS)

#define IDX_CAPACITY (8 * 1024 * 1024)
__device__ int g_idx32[IDX_CAPACITY];
__device__ int g_idx_is64;

// Detect index dtype: int64 indices in [0,2^31) have all-zero odd int32 words.
__global__ void detect_idx_dtype_kernel(const int* __restrict__ idx_words, int n_words)
{
    __shared__ int nz;
    if (threadIdx.x == 0) nz = 0;
    __syncthreads();
    int local = 0;
    for (int i = threadIdx.x; i < n_words / 2; i += blockDim.x)
        if (idx_words[2 * i + 1] != 0) local = 1;
    if (local) atomicOr(&nz, 1);
    __syncthreads();
    if (threadIdx.x == 0) g_idx_is64 = (nz == 0) ? 1 : 0;
}

// Normalize indices to clamped int32 in scratch.
__global__ void convert_idx_kernel(const int* __restrict__ words, int n_idx, int vocab)
{
    int is64 = g_idx_is64;
    int i = blockIdx.x * blockDim.x + threadIdx.x;
    if (i < n_idx) {
        int v = is64 ? words[2 * i] : words[i];
        v = min(max(v, 0), vocab - 1);
        g_idx32[i] = v;
    }
}

__global__ __launch_bounds__(256, 6) void attn_agg_kernel(
    const float4* __restrict__ tbl4,
    const float*  __restrict__ attn_w,
    float4*       __restrict__ out4,
    int n_nodes)
{
    // Lane-private staging: stage[warp][row][lane]; each lane touches only its
    // own 16B slot -> no cross-lane smem sharing, no sync, no bank conflicts.
    __shared__ float4 stage[WARPS_PER_BLOCK][SMEM_ROWS][32];

    int warp = threadIdx.x >> 5;
    int lane = threadIdx.x & 31;
    int node = blockIdx.x * WARPS_PER_BLOCK + warp;
    if (node >= n_nodes) return;

    float4 w4 = ((const float4*)attn_w)[lane];

    // Coalesced index fetch: lanes 0..9 load this node's 10 indices.
    int myidx = 0;
    if (lane < K_NEIGH) myidx = g_idx32[node * K_NEIGH + lane];
    unsigned mybase = (unsigned)myidx * 32u;   // float4 elements per row = 32

    float  s[K_NEIGH];
    float4 fr[REG_ROWS];

    // Gather: 512B coalesced row per k; partial dot per lane; rows beyond
    // REG_ROWS go straight to smem, freeing registers for occupancy.
    #pragma unroll
    for (int k = 0; k < K_NEIGH; k++) {
        unsigned b = __shfl_sync(0xffffffffu, mybase, k) + (unsigned)lane;
        float4 f = tbl4[b];
        s[k] = f.x * w4.x + f.y * w4.y + f.z * w4.z + f.w * w4.w;
        if (k < REG_ROWS) fr[k] = f;
        else              stage[warp][k - REG_ROWS][lane] = f;
    }

    // Batched warp reduction: 10 scores in 5 shuffle rounds.
    #pragma unroll
    for (int off = 16; off > 0; off >>= 1) {
        #pragma unroll
        for (int k = 0; k < K_NEIGH; k++)
            s[k] += __shfl_xor_sync(0xffffffffu, s[k], off);
    }

    // Softmax over K (every lane holds the full score vector).
    float m = s[0];
    #pragma unroll
    for (int k = 1; k < K_NEIGH; k++) m = fmaxf(m, s[k]);
    float sum = 0.0f;
    #pragma unroll
    for (int k = 0; k < K_NEIGH; k++) { s[k] = __expf(s[k] - m); sum += s[k]; }
    float inv = __frcp_rn(sum);

    // Weighted sum: register rows, then smem-staged rows.
    float4 acc = make_float4(0.f, 0.f, 0.f, 0.f);
    #pragma unroll
    for (int k = 0; k < REG_ROWS; k++) {
        float wk = s[k] * inv;
        acc.x = fmaf(wk, fr[k].x, acc.x);
        acc.y = fmaf(wk, fr[k].y, acc.y);
        acc.z = fmaf(wk, fr[k].z, acc.z);
        acc.w = fmaf(wk, fr[k].w, acc.w);
    }
    #pragma unroll
    for (int k = REG_ROWS; k < K_NEIGH; k++) {
        float4 f = stage[warp][k - REG_ROWS][lane];
        float wk = s[k] * inv;
        acc.x = fmaf(wk, f.x, acc.x);
        acc.y = fmaf(wk, f.y, acc.y);
        acc.z = fmaf(wk, f.z, acc.z);
        acc.w = fmaf(wk, f.w, acc.w);
    }

    // Streaming store: don't let the 51MB output evict the table from L2.
    __stcs(&out4[(size_t)node * 32 + lane], acc);
}

extern "C" void kernel_launch(void* const* d_in, const int* in_sizes, int n_in,
                              void* d_out, int out_size)
{
    // Identify inputs by element count:
    //   attn_w: exactly 128; table: large multiple of 128; idx: the remaining one.
    int ti = -1, wi = -1, ii = -1;
    for (int i = 0; i < n_in; i++) {
        if (in_sizes[i] == 128 && wi < 0) { wi = i; continue; }
        if (in_sizes[i] >= (1 << 20) && (in_sizes[i] % 128) == 0 && ti < 0) { ti = i; continue; }
    }
    for (int i = 0; i < n_in; i++) if (i != ti && i != wi) { ii = i; break; }

    const float* table  = (const float*)d_in[ti];
    const float* attn_w = (const float*)d_in[wi];
    const int*   nidx   = (const int*)d_in[ii];

    int n_idx_elems = in_sizes[ii];
    int n_nodes = n_idx_elems / K_NEIGH;
    int vocab   = in_sizes[ti] / 128;

    // 1) detect index dtype (scans first 2048 int32 words)
    int n_words = n_idx_elems < 2048 ? n_idx_elems : 2048;
    detect_idx_dtype_kernel<<<1, 256>>>(nidx, n_words);

    // 2) normalize indices into int32 scratch
    int cblocks = (n_idx_elems + 255) / 256;
    convert_idx_kernel<<<cblocks, 256>>>(nidx, n_idx_elems, vocab);

    // 3) main kernel: 8 warps (8 nodes) per block
    int blocks = (n_nodes + WARPS_PER_BLOCK - 1) / WARPS_PER_BLOCK;
    attn_agg_kernel<<<blocks, 256>>>((const float4*)table, attn_w,
                                     (float4*)d_out, n_nodes);
}

// round 5
// speedup vs baseline: 1.5360x; 1.5360x over previous
#include <cuda_runtime.h>

// AttentionAggregator: out[n] = sum_k softmax_k(feats[n,k]·w) * feats[n,k],
// feats[n,k] = embed_table[neigh_idx[n,k]].
// table [VOCAB,128] f32, attn_w [128] f32, neigh_idx [N,10] (int32 or int64), out [N,128] f32.
//
// R5: 2 warps per node, each owning 64 dims (float2/lane). Gathered rows stay
// register-resident (20 regs instead of 40) -> ~48 regs -> ~42 warps/SM.
// One smem exchange + __syncthreads combines the two warps' partial scores.

#define K_NEIGH 10
#define WARPS_PER_BLOCK 8   // 4 nodes per 256-thread block

__device__ int g_idx_is64;

// Detect index dtype: int64 indices in [0,2^31) have all-zero odd int32 words.
__global__ void detect_idx_dtype_kernel(const int* __restrict__ idx_words, int n_words)
{
    __shared__ int nz;
    if (threadIdx.x == 0) nz = 0;
    __syncthreads();
    int local = 0;
    for (int i = threadIdx.x; i < n_words / 2; i += blockDim.x)
        if (idx_words[2 * i + 1] != 0) local = 1;
    if (local) atomicOr(&nz, 1);
    __syncthreads();
    if (threadIdx.x == 0) g_idx_is64 = (nz == 0) ? 1 : 0;
}

__global__ __launch_bounds__(256, 5) void attn_agg_kernel(
    const float* __restrict__ table,
    const float* __restrict__ attn_w,
    const void* __restrict__ neigh_idx,
    float* __restrict__ out,
    int n_nodes,
    int vocab)
{
    // Per-warp partial score exchange buffer.
    __shared__ float psum[WARPS_PER_BLOCK][K_NEIGH];

    int warp = threadIdx.x >> 5;
    int lane = threadIdx.x & 31;

    int gwarp = blockIdx.x * WARPS_PER_BLOCK + warp;
    int node  = gwarp >> 1;          // two warps per node
    int half  = gwarp & 1;           // which 64-dim half this warp owns
    bool active = (node < n_nodes);

    const int is64 = g_idx_is64;     // uniform

    // attn_w half for this warp: float2 per lane.
    float2 w2 = active ? ((const float2*)attn_w)[half * 32 + lane]
                       : make_float2(0.f, 0.f);

    // Load this node's 10 indices (lanes 0..9), convert to unsigned byte offset
    // of the row half, broadcast via shfl.
    unsigned mybase = 0;
    if (active && lane < K_NEIGH) {
        int r;
        if (is64) r = (int)((const long long*)neigh_idx)[(size_t)node * K_NEIGH + lane];
        else      r = ((const int*)neigh_idx)[(size_t)node * K_NEIGH + lane];
        r = min(max(r, 0), vocab - 1);
        mybase = (unsigned)r * 512u + (unsigned)half * 256u;   // bytes
    }

    float2 f[K_NEIGH];
    float  s[K_NEIGH];

    // Gather: each warp reads 256B (32 x float2) of each of the 10 rows.
    // 10 independent loads -> MLP=10. Partial dot per lane over its 2 dims.
    #pragma unroll
    for (int k = 0; k < K_NEIGH; k++) {
        unsigned off = __shfl_sync(0xffffffffu, mybase, k) + (unsigned)(lane * 8);
        if (active) {
            f[k] = *(const float2*)((const char*)table + off);
        } else {
            f[k] = make_float2(0.f, 0.f);
        }
        s[k] = f[k].x * w2.x + f[k].y * w2.y;
    }

    // Warp-level reduction of all 10 partials (5 shuffle rounds).
    #pragma unroll
    for (int off = 16; off > 0; off >>= 1) {
        #pragma unroll
        for (int k = 0; k < K_NEIGH; k++)
            s[k] += __shfl_xor_sync(0xffffffffu, s[k], off);
    }

    // Cross-warp combine: lane 0 publishes this warp's 10 partial sums.
    if (lane == 0) {
        #pragma unroll
        for (int k = 0; k < K_NEIGH; k++) psum[warp][k] = s[k];
    }
    __syncthreads();

    // Add partner warp's partials (broadcast LDS, conflict-free).
    int partner = warp ^ 1;
    #pragma unroll
    for (int k = 0; k < K_NEIGH; k++) s[k] += psum[partner][k];

    // Softmax over K (replicated in every lane).
    float m = s[0];
    #pragma unroll
    for (int k = 1; k < K_NEIGH; k++) m = fmaxf(m, s[k]);
    float sum = 0.0f;
    #pragma unroll
    for (int k = 0; k < K_NEIGH; k++) { s[k] = __expf(s[k] - m); sum += s[k]; }
    float inv = __frcp_rn(sum);

    // Weighted sum over register-resident half-rows.
    float2 acc = make_float2(0.f, 0.f);
    #pragma unroll
    for (int k = 0; k < K_NEIGH; k++) {
        float wk = s[k] * inv;
        acc.x = fmaf(wk, f[k].x, acc.x);
        acc.y = fmaf(wk, f[k].y, acc.y);
    }

    if (active) {
        ((float2*)out)[(size_t)node * 64 + half * 32 + lane] = acc;
    }
}

extern "C" void kernel_launch(void* const* d_in, const int* in_sizes, int n_in,
                              void* d_out, int out_size)
{
    // Identify inputs by element count:
    //   attn_w: exactly 128; table: large multiple of 128; idx: the remaining one.
    int ti = -1, wi = -1, ii = -1;
    for (int i = 0; i < n_in; i++) {
        if (in_sizes[i] == 128 && wi < 0) { wi = i; continue; }
        if (in_sizes[i] >= (1 << 20) && (in_sizes[i] % 128) == 0 && ti < 0) { ti = i; continue; }
    }
    for (int i = 0; i < n_in; i++) if (i != ti && i != wi) { ii = i; break; }

    const float* table  = (const float*)d_in[ti];
    const float* attn_w = (const float*)d_in[wi];
    const void*  nidx   = d_in[ii];

    int n_idx_elems = in_sizes[ii];
    int n_nodes = n_idx_elems / K_NEIGH;
    int vocab   = in_sizes[ti] / 128;

    // 1) detect index dtype (scans first 2048 int32 words)
    int n_words = n_idx_elems < 2048 ? n_idx_elems : 2048;
    detect_idx_dtype_kernel<<<1, 256>>>((const int*)nidx, n_words);

    // 2) main kernel: 8 warps per block = 4 nodes per block
    int warps_needed = 2 * n_nodes;
    int blocks = (warps_needed + WARPS_PER_BLOCK - 1) / WARPS_PER_BLOCK;
    attn_agg_kernel<<<blocks, 256>>>(table, attn_w, nidx, (float*)d_out,
                                     n_nodes, vocab);
}

// round 6
// speedup vs baseline: 2.8177x; 1.8344x over previous
#include <cuda_runtime.h>

// AttentionAggregator: out[n] = sum_k softmax_k(feats[n,k]·w) * feats[n,k],
// feats[n,k] = embed_table[neigh_idx[n,k]].
// table [VOCAB,128] f32, attn_w [128] f32, neigh_idx [N,10] (int32 or int64), out [N,128] f32.
//
// R6: warp-per-node (R3 layout) + online softmax in 2 groups of 5 neighbors.
// Only 5 gathered rows live at once -> ~50 regs instead of 64 -> more warps/SM.
// No smem, no barriers, single kernel launch (dtype detect inlined via ballot).

#define K_NEIGH 10
#define GROUP 5

__global__ __launch_bounds__(256) void attn_agg_kernel(
    const float* __restrict__ table,
    const float* __restrict__ attn_w,
    const int*   __restrict__ idx_words,   // raw index buffer viewed as int32 words
    float* __restrict__ out,
    int n_nodes,
    int vocab)
{
    int warp = threadIdx.x >> 5;
    int lane = threadIdx.x & 31;
    int node = blockIdx.x * 8 + warp;
    if (node >= n_nodes) return;

    // Inline dtype detection: int64 indices in [0,2^31) have all-zero odd
    // int32 words; an int32 buffer has random vocab ids there (never all 0).
    // One coalesced 64B read (L2-broadcast) + ballot. Uniform per warp.
    int oddw = 0;
    if (lane < 16) oddw = idx_words[2 * lane + 1];
    bool is32 = __ballot_sync(0xffffffffu, oddw != 0) != 0u;

    // Load this node's K indices (lanes 0..9), convert to byte offset of row.
    unsigned mybase = 0;
    if (lane < K_NEIGH) {
        int r;
        if (is32) r = idx_words[node * K_NEIGH + lane];
        else      r = (int)((const long long*)idx_words)[(size_t)node * K_NEIGH + lane];
        r = min(max(r, 0), vocab - 1);
        mybase = (unsigned)r * 512u;          // 128 floats per row
    }

    float4 w4 = ((const float4*)attn_w)[lane];

    float4 f[GROUP];
    float  s[GROUP];

    float  m, d;
    float4 acc;

    // ---- Group A: neighbors 0..4 ----
    #pragma unroll
    for (int k = 0; k < GROUP; k++) {
        unsigned off = __shfl_sync(0xffffffffu, mybase, k) + (unsigned)(lane * 16);
        f[k] = *(const float4*)((const char*)table + off);
        s[k] = f[k].x * w4.x + f[k].y * w4.y + f[k].z * w4.z + f[k].w * w4.w;
    }
    #pragma unroll
    for (int off = 16; off > 0; off >>= 1) {
        #pragma unroll
        for (int k = 0; k < GROUP; k++)
            s[k] += __shfl_xor_sync(0xffffffffu, s[k], off);
    }
    m = s[0];
    #pragma unroll
    for (int k = 1; k < GROUP; k++) m = fmaxf(m, s[k]);
    d = 0.0f;
    acc = make_float4(0.f, 0.f, 0.f, 0.f);
    #pragma unroll
    for (int k = 0; k < GROUP; k++) {
        float e = __expf(s[k] - m);
        d += e;
        acc.x = fmaf(e, f[k].x, acc.x);
        acc.y = fmaf(e, f[k].y, acc.y);
        acc.z = fmaf(e, f[k].z, acc.z);
        acc.w = fmaf(e, f[k].w, acc.w);
    }

    // ---- Group B: neighbors 5..9 (reuse f/s registers) ----
    #pragma unroll
    for (int k = 0; k < GROUP; k++) {
        unsigned off = __shfl_sync(0xffffffffu, mybase, GROUP + k) + (unsigned)(lane * 16);
        f[k] = *(const float4*)((const char*)table + off);
        s[k] = f[k].x * w4.x + f[k].y * w4.y + f[k].z * w4.z + f[k].w * w4.w;
    }
    #pragma unroll
    for (int off = 16; off > 0; off >>= 1) {
        #pragma unroll
        for (int k = 0; k < GROUP; k++)
            s[k] += __shfl_xor_sync(0xffffffffu, s[k], off);
    }
    float mB = s[0];
    #pragma unroll
    for (int k = 1; k < GROUP; k++) mB = fmaxf(mB, s[k]);

    // Rescale running accumulator to the new max (flash-attention update).
    float newm  = fmaxf(m, mB);
    float scale = __expf(m - newm);
    d *= scale;
    acc.x *= scale; acc.y *= scale; acc.z *= scale; acc.w *= scale;

    #pragma unroll
    for (int k = 0; k < GROUP; k++) {
        float e = __expf(s[k] - newm);
        d += e;
        acc.x = fmaf(e, f[k].x, acc.x);
        acc.y = fmaf(e, f[k].y, acc.y);
        acc.z = fmaf(e, f[k].z, acc.z);
        acc.w = fmaf(e, f[k].w, acc.w);
    }

    float inv = __frcp_rn(d);
    acc.x *= inv; acc.y *= inv; acc.z *= inv; acc.w *= inv;

    // Streaming store: keep the 51MB output from evicting the table in L2.
    __stcs(&((float4*)out)[(size_t)node * 32 + lane], acc);
}

extern "C" void kernel_launch(void* const* d_in, const int* in_sizes, int n_in,
                              void* d_out, int out_size)
{
    // Identify inputs by element count:
    //   attn_w: exactly 128; table: large multiple of 128; idx: the remaining one.
    int ti = -1, wi = -1, ii = -1;
    for (int i = 0; i < n_in; i++) {
        if (in_sizes[i] == 128 && wi < 0) { wi = i; continue; }
        if (in_sizes[i] >= (1 << 20) && (in_sizes[i] % 128) == 0 && ti < 0) { ti = i; continue; }
    }
    for (int i = 0; i < n_in; i++) if (i != ti && i != wi) { ii = i; break; }

    const float* table  = (const float*)d_in[ti];
    const float* attn_w = (const float*)d_in[wi];
    const int*   nidx   = (const int*)d_in[ii];

    int n_nodes = in_sizes[ii] / K_NEIGH;
    int vocab   = in_sizes[ti] / 128;

    int blocks = (n_nodes + 7) / 8;     // 8 warps = 8 nodes per 256-thread block
    attn_agg_kernel<<<blocks, 256>>>(table, attn_w, nidx, (float*)d_out,
                                     n_nodes, vocab);
}